// round 7
// baseline (speedup 1.0000x reference)
#include <cuda_runtime.h>
#include <math.h>
#include <string.h>

#define D 64
#define EPS_M 1e-7f
#define N_MAX 100001
#define NB 4            // nodes per warp-chunk

typedef unsigned long long u64;

__device__ float g_WT[D * D];       // g_WT[d*64 + c] = W[c][d]
__device__ int   g_off[N_MAX + 1];  // CSR offsets into sorted dst

// ---- single pre-kernel: CSR offsets + W transpose ----
__global__ void prep_kernel(const int* __restrict__ dst,
                            const float* __restrict__ W,
                            int n_nodes, int n_edges)
{
    const int i = blockIdx.x * blockDim.x + threadIdx.x;
    if (i < D * D) {
        int r = i >> 6, c = i & 63;       // W[r][c]
        g_WT[c * D + r] = W[i];
    }
    if (i <= n_nodes) {
        if (i == n_nodes) { g_off[i] = n_edges; }
        else {
            int lo = 0, hi = n_edges;
            while (lo < hi) { int mid = (lo + hi) >> 1; if (dst[mid] < i) lo = mid + 1; else hi = mid; }
            g_off[i] = lo;
        }
    }
}

// packed add + relu + exp; eps folded out (agg = sme/se + eps at the end)
__device__ __forceinline__ void edge_step(const ulonglong2 av, const ulonglong2 bv,
                                          float4& se, float4& sme)
{
    u64 s01, s23;
    asm("add.rn.f32x2 %0, %1, %2;" : "=l"(s01) : "l"(av.x), "l"(bv.x));
    asm("add.rn.f32x2 %0, %1, %2;" : "=l"(s23) : "l"(av.y), "l"(bv.y));
    float x0, x1, x2, x3;
    asm("mov.b64 {%0, %1}, %2;" : "=f"(x0), "=f"(x1) : "l"(s01));
    asm("mov.b64 {%0, %1}, %2;" : "=f"(x2), "=f"(x3) : "l"(s23));
    const float r0 = fmaxf(x0, 0.f), r1 = fmaxf(x1, 0.f);
    const float r2 = fmaxf(x2, 0.f), r3 = fmaxf(x3, 0.f);
    const float p0 = __expf(r0), p1 = __expf(r1);
    const float p2 = __expf(r2), p3 = __expf(r3);
    se.x += p0; se.y += p1; se.z += p2; se.w += p3;
    sme.x = fmaf(r0, p0, sme.x); sme.y = fmaf(r1, p1, sme.y);
    sme.z = fmaf(r2, p2, sme.z); sme.w = fmaf(r3, p3, sme.w);
}

// ---- main kernel ----
__global__ void __launch_bounds__(256, 6) genconv_kernel(
    const float* __restrict__ nf,     // [N, 64]
    const float* __restrict__ ef,     // [E, 64]
    const float* __restrict__ bvec,   // [64]
    const float* __restrict__ scale,  // [1]
    const int*   __restrict__ src,    // [E]
    float*       __restrict__ out,    // [N, 64]
    int n_nodes)
{
    // sWTp layout (FIXED): for d-pair dp, lane l, k in 0..3 with k = 2*doff + coff:
    //   sWTp[dp*128 + l*4 + k] = WT[(2*dp + doff)*64 + (2*l + coff)]
    // so a lane's 16B read gives {W_d[2l], W_d[2l+1], W_d1[2l], W_d1[2l+1]}.
    __shared__ float sWTp[D * D];           // 16 KB
    __shared__ float s_featd[8][NB][2 * D]; // 16 KB, feat duplicated {f,f}

    const int lane = threadIdx.x & 31;
    const int wim  = threadIdx.x >> 5;
    const int q    = lane & 15;
    const int eo   = lane >> 4;           // half-warp edge offset
    const int c4   = q * 4;
    const int gw   = (blockIdx.x * blockDim.x + threadIdx.x) >> 5;
    const int nwarps = (gridDim.x * blockDim.x) >> 5;

    // stage W in pair-interleaved layout (corrected indexing)
    for (int i = threadIdx.x; i < D * D; i += 256) {
        const int dp   = i >> 7;          // d-pair
        const int rem  = i & 127;
        const int l    = rem >> 2;        // lane slot (channel pair 2l,2l+1)
        const int k    = rem & 3;
        const int doff = k >> 1;
        const int coff = k & 1;
        sWTp[i] = g_WT[(2 * dp + doff) * D + (2 * l + coff)];
    }
    __syncthreads();

    const float sc = scale[0];
    u64 bvp;            // packed bias for this lane's channel pair
    {
        float2 bvv = *(const float2*)(bvec + lane * 2);
        memcpy(&bvp, &bvv, 8);
    }
    const int nchunks = (n_nodes + NB - 1) / NB;

    for (int chunk = gw; chunk < nchunks; chunk += nwarps) {
        const int base = chunk * NB;

        #pragma unroll
        for (int i = 0; i < NB; ++i) {
            const int node = base + i;
            float4 se  = make_float4(0.f, 0.f, 0.f, 0.f);
            float4 sme = make_float4(0.f, 0.f, 0.f, 0.f);
            float4 h4  = make_float4(0.f, 0.f, 0.f, 0.f);

            if (node < n_nodes) {
                h4 = *(const float4*)(nf + node * D + c4);
                const int s    = g_off[node];
                const int eend = g_off[node + 1];
                int e = s + eo;
                for (; e + 2 < eend; e += 4) {
                    const int sp0 = __ldg(&src[e]);
                    const int sp1 = __ldg(&src[e + 2]);
                    const ulonglong2 b0 = __ldcs((const ulonglong2*)(ef + (size_t)e * D + c4));
                    const ulonglong2 b1 = __ldcs((const ulonglong2*)(ef + (size_t)(e + 2) * D + c4));
                    const ulonglong2 a0 = *(const ulonglong2*)(nf + sp0 * D + c4);
                    const ulonglong2 a1 = *(const ulonglong2*)(nf + sp1 * D + c4);
                    edge_step(a0, b0, se, sme);
                    edge_step(a1, b1, se, sme);
                }
                if (e < eend) {
                    const int sp0 = __ldg(&src[e]);
                    const ulonglong2 b0 = __ldcs((const ulonglong2*)(ef + (size_t)e * D + c4));
                    const ulonglong2 a0 = *(const ulonglong2*)(nf + sp0 * D + c4);
                    edge_step(a0, b0, se, sme);
                }
            }
            // combine edge-halves
            se.x += __shfl_xor_sync(0xffffffffu, se.x, 16);
            se.y += __shfl_xor_sync(0xffffffffu, se.y, 16);
            se.z += __shfl_xor_sync(0xffffffffu, se.z, 16);
            se.w += __shfl_xor_sync(0xffffffffu, se.w, 16);
            sme.x += __shfl_xor_sync(0xffffffffu, sme.x, 16);
            sme.y += __shfl_xor_sync(0xffffffffu, sme.y, 16);
            sme.z += __shfl_xor_sync(0xffffffffu, sme.z, 16);
            sme.w += __shfl_xor_sync(0xffffffffu, sme.w, 16);

            float4 agg;   // eps folded back in here (exact)
            agg.x = (se.x > 0.f) ? (sme.x / se.x + EPS_M) : 0.f;
            agg.y = (se.y > 0.f) ? (sme.y / se.y + EPS_M) : 0.f;
            agg.z = (se.z > 0.f) ? (sme.z / se.z + EPS_M) : 0.f;
            agg.w = (se.w > 0.f) ? (sme.w / se.w + EPS_M) : 0.f;

            float a2 = fmaf(agg.x, agg.x, fmaf(agg.y, agg.y, fmaf(agg.z, agg.z, agg.w * agg.w)));
            float h2 = fmaf(h4.x, h4.x, fmaf(h4.y, h4.y, fmaf(h4.z, h4.z, h4.w * h4.w)));
            #pragma unroll
            for (int o = 8; o > 0; o >>= 1) {
                a2 += __shfl_xor_sync(0xffffffffu, a2, o);
                h2 += __shfl_xor_sync(0xffffffffu, h2, o);
            }

            const float coef = (sqrtf(h2) * sc) / fmaxf(sqrtf(a2), 1e-12f);
            if (lane < 16) {
                const float f0 = fmaf(agg.x, coef, h4.x);
                const float f1 = fmaf(agg.y, coef, h4.y);
                const float f2 = fmaf(agg.z, coef, h4.z);
                const float f3 = fmaf(agg.w, coef, h4.w);
                // duplicated store: [2c]=[2c+1]=f_c
                *(float4*)&s_featd[wim][i][2 * c4]     = make_float4(f0, f0, f1, f1);
                *(float4*)&s_featd[wim][i][2 * c4 + 4] = make_float4(f2, f2, f3, f3);
            }
        }
        __syncwarp();

        // packed-FMA2 mini-GEMM: acc[i] (u64 = channels 2*lane, 2*lane+1)
        u64 acc[NB];
        #pragma unroll
        for (int i = 0; i < NB; ++i) acc[i] = bvp;

        #pragma unroll
        for (int dp = 0; dp < D / 2; ++dp) {
            // wv.x = {W_{2dp}[2l], W_{2dp}[2l+1]}, wv.y = {W_{2dp+1}[2l], W_{2dp+1}[2l+1]}
            const ulonglong2 wv = *(const ulonglong2*)(sWTp + dp * 128 + lane * 4);
            #pragma unroll
            for (int i = 0; i < NB; ++i) {
                // f2.x = {f_{2dp}, f_{2dp}}, f2.y = {f_{2dp+1}, f_{2dp+1}} (broadcast)
                const ulonglong2 f2 = *(const ulonglong2*)(&s_featd[wim][i][dp * 4]);
                asm("fma.rn.f32x2 %0, %1, %2, %0;" : "+l"(acc[i]) : "l"(f2.x), "l"(wv.x));
                asm("fma.rn.f32x2 %0, %1, %2, %0;" : "+l"(acc[i]) : "l"(f2.y), "l"(wv.y));
            }
        }
        #pragma unroll
        for (int i = 0; i < NB; ++i)
            if (base + i < n_nodes)
                *(u64*)(out + (size_t)(base + i) * D + lane * 2) = acc[i];
        __syncwarp();   // protect s_featd WAR for next chunk
    }
}

extern "C" void kernel_launch(void* const* d_in, const int* in_sizes, int n_in,
                              void* d_out, int out_size)
{
    const float* nf    = (const float*)d_in[0];
    const float* ef    = (const float*)d_in[1];
    const float* W     = (const float*)d_in[2];
    const float* bvec  = (const float*)d_in[3];
    const float* scale = (const float*)d_in[4];
    const int*   src   = (const int*)d_in[5];
    const int*   dst   = (const int*)d_in[6];
    float* out = (float*)d_out;

    const int n_nodes = in_sizes[0] / D;
    const int n_edges = in_sizes[5];

    prep_kernel<<<(n_nodes + 256) / 256, 256>>>(dst, W, n_nodes, n_edges);
    genconv_kernel<<<1480, 256>>>(nf, ef, bvec, scale, src, out, n_nodes);
}